// round 5
// baseline (speedup 1.0000x reference)
#include <cuda_runtime.h>
#include <cuda_bf16.h>
#include <cstdint>

// ============================================================================
// VLunchboxMHSA — linear-attention reassociation, tensor-core k1.
// R5: pre-converted bf16 hi/lo operands + cp.async double-buffered k1;
//     k3 fused into k4.
// ============================================================================

#define SCALE 0.125f

__device__ float d_K[4 * 2048 * 512];            // [b*m, h*64+d]
__device__ float d_KV[32 * 64 * 64];             // [bh, d, l]
__device__ float d_Wfin[4 * 512 * 64];           // [b, c, e]
__device__ __nv_bfloat16 d_xh[4 * 2048 * 512];   // x hi, [b*m][c]
__device__ __nv_bfloat16 d_xl[4 * 2048 * 512];   // x lo
__device__ __nv_bfloat16 d_wkh[512 * 512];       // Wk^T hi, [n=hd][k=c]
__device__ __nv_bfloat16 d_wkl[512 * 512];       // Wk^T lo

// ---------------- helpers ---------------------------------------------------
__device__ __forceinline__ uint32_t smem_u32(const void* p) {
    uint32_t a;
    asm("{ .reg .u64 t; cvta.to.shared.u64 t, %1; cvt.u32.u64 %0, t; }"
        : "=r"(a) : "l"(p));
    return a;
}
#define CP_ASYNC16(dst, src) \
    asm volatile("cp.async.ca.shared.global [%0], [%1], 16;" :: "r"(dst), "l"(src))
#define CP_COMMIT() asm volatile("cp.async.commit_group;" ::: "memory")
#define CP_WAIT(n)  asm volatile("cp.async.wait_group %0;" :: "n"(n) : "memory")

__device__ __forceinline__ void mma16816(float* c, const uint32_t* a,
                                         uint32_t b0, uint32_t b1) {
    asm volatile(
        "mma.sync.aligned.m16n8k16.row.col.f32.bf16.bf16.f32 "
        "{%0,%1,%2,%3}, {%4,%5,%6,%7}, {%8,%9}, {%0,%1,%2,%3};"
        : "+f"(c[0]), "+f"(c[1]), "+f"(c[2]), "+f"(c[3])
        : "r"(a[0]), "r"(a[1]), "r"(a[2]), "r"(a[3]), "r"(b0), "r"(b1));
}

// split 8 floats into hi/lo bf16 (4x bf16x2 each)
__device__ __forceinline__ void split8(const float* f, uint4& hi, uint4& lo) {
    uint32_t h[4], l[4];
#pragma unroll
    for (int i = 0; i < 4; i++) {
        float2 p = make_float2(f[2 * i], f[2 * i + 1]);
        __nv_bfloat162 hb = __float22bfloat162_rn(p);
        float2 hr = __bfloat1622float2(hb);
        __nv_bfloat162 lb =
            __float22bfloat162_rn(make_float2(p.x - hr.x, p.y - hr.y));
        h[i] = *(uint32_t*)&hb;
        l[i] = *(uint32_t*)&lb;
    }
    hi = make_uint4(h[0], h[1], h[2], h[3]);
    lo = make_uint4(l[0], l[1], l[2], l[3]);
}

// packed f32x2 helpers (SIMT tail kernels)
__device__ __forceinline__ void fma2(unsigned long long& d,
                                     unsigned long long a,
                                     unsigned long long b) {
    asm("fma.rn.f32x2 %0, %1, %2, %0;" : "+l"(d) : "l"(a), "l"(b));
}
__device__ __forceinline__ unsigned long long splat2(float f) {
    unsigned long long r;
    unsigned u = __float_as_uint(f);
    asm("mov.b64 %0, {%1, %1};" : "=l"(r) : "r"(u));
    return r;
}

// ---------------------------------------------------------------------------
// k0: zero atomic-accumulated buffers
// ---------------------------------------------------------------------------
__global__ void k0_zero(float* __restrict__ out) {
    int idx = blockIdx.x * blockDim.x + threadIdx.x;
    if (idx < 32 * 64 * 64)  d_KV[idx]   = 0.f;
    if (idx < 4 * 512 * 64)  d_Wfin[idx] = 0.f;
    if (idx < 4 * 2048 * 64) out[idx]    = 0.f;
}

// ---------------------------------------------------------------------------
// p_cvt_x: x fp32 -> (xh, xl) bf16, same layout.  grid 2048 x 256
// ---------------------------------------------------------------------------
__global__ __launch_bounds__(256) void p_cvt_x(const float* __restrict__ x) {
    size_t base = ((size_t)blockIdx.x * 256 + threadIdx.x) * 8;
    float f[8];
    *(float4*)(f)     = *(const float4*)(x + base);
    *(float4*)(f + 4) = *(const float4*)(x + base + 4);
    uint4 hi, lo;
    split8(f, hi, lo);
    *(uint4*)(d_xh + base) = hi;
    *(uint4*)(d_xl + base) = lo;
}

// ---------------------------------------------------------------------------
// p_cvt_w: gather Wk columns of qkv -> (wkh, wkl) [n][k] bf16.  grid 128 x 256
// ---------------------------------------------------------------------------
__global__ __launch_bounds__(256) void p_cvt_w(const float* __restrict__ qkv) {
    int gid = blockIdx.x * 256 + threadIdx.x;   // 0..32767
    int n   = gid >> 6;
    int kb  = (gid & 63) * 8;
    int col = ((n >> 6) << 7) + 64 + (n & 63);
    float f[8];
#pragma unroll
    for (int j = 0; j < 8; j++)
        f[j] = qkv[(size_t)(kb + j) * 1024 + col];
    uint4 hi, lo;
    split8(f, hi, lo);
    *(uint4*)(d_wkh + (size_t)n * 512 + kb) = hi;
    *(uint4*)(d_wkl + (size_t)n * 512 + kb) = lo;
}

// ---------------------------------------------------------------------------
// k1_mma: K = x @ Wk  (M=8192, N=512, K=512) bf16 split-precision tensor core.
//   Pre-converted operands, cp.async double-buffered smem.
//   grid (4 n-tiles, 64 m-tiles), 256 thr, CTA tile 128x128, k-chunks of 32.
//   Tile buffer: [128 rows][40 bf16] (80 B row stride, 16B-aligned, conflict-free)
// ---------------------------------------------------------------------------
#define TS 10240                       // bytes per tile buffer (128*40*2)
#define K1_SMEM (8 * TS)               // 4 arrays x 2 buffers = 81920 B
#define ARR_AH 0
#define ARR_AL 1
#define ARR_BH 2
#define ARR_BL 3

__global__ __launch_bounds__(256, 2) void k1_mma(int dummy) {
    extern __shared__ __align__(16) char sm[];
    const uint32_t sbase = smem_u32(sm);

    const int tid  = threadIdx.x;
    const int wid  = tid >> 5;
    const int lane = tid & 31;
    const int bm = blockIdx.y * 128;
    const int bn = blockIdx.x * 128;
    const int warp_m = (wid & 3) * 32;
    const int warp_n = (wid >> 2) * 64;
    const int tg = lane >> 2;   // 0..7
    const int tq = lane & 3;    // 0..3

    float acc[2][8][4];
#pragma unroll
    for (int mt = 0; mt < 2; mt++)
#pragma unroll
        for (int nt = 0; nt < 8; nt++)
#pragma unroll
            for (int i = 0; i < 4; i++) acc[mt][nt][i] = 0.f;

    // cp.async granule coordinates (2 granules of 16B per array per thread)
    const int g_row0 = tid >> 2;            // granule tid
    const int g_c0   = tid & 3;
    const int g_row1 = (tid + 256) >> 2;    // granule tid+256
    const int g_c1   = tid & 3;             // (tid+256)&3 == tid&3

    // issue one chunk's copies into buffer `buf`
    auto issue = [&](int kc, int buf) {
        const int k0 = kc * 32;
#pragma unroll
        for (int i = 0; i < 2; i++) {
            const int row = i ? g_row1 : g_row0;
            const int c16 = i ? g_c1 : g_c0;
            const uint32_t doff = row * 80 + c16 * 16;
            const size_t aoff = (((size_t)(bm + row)) << 9) + k0 + c16 * 8;
            const size_t boff = (((size_t)(bn + row)) << 9) + k0 + c16 * 8;
            CP_ASYNC16(sbase + (ARR_AH * 2 + buf) * TS + doff,
                       (const char*)d_xh + aoff * 2);
            CP_ASYNC16(sbase + (ARR_AL * 2 + buf) * TS + doff,
                       (const char*)d_xl + aoff * 2);
            CP_ASYNC16(sbase + (ARR_BH * 2 + buf) * TS + doff,
                       (const char*)d_wkh + boff * 2);
            CP_ASYNC16(sbase + (ARR_BL * 2 + buf) * TS + doff,
                       (const char*)d_wkl + boff * 2);
        }
        CP_COMMIT();
    };

    issue(0, 0);

    for (int kc = 0; kc < 16; kc++) {
        const int buf = kc & 1;
        if (kc < 15) {
            issue(kc + 1, buf ^ 1);
            CP_WAIT(1);
        } else {
            CP_WAIT(0);
        }
        __syncthreads();

        const __nv_bfloat16(*Ah)[40] =
            (const __nv_bfloat16(*)[40])(sm + (ARR_AH * 2 + buf) * TS);
        const __nv_bfloat16(*Al)[40] =
            (const __nv_bfloat16(*)[40])(sm + (ARR_AL * 2 + buf) * TS);
        const __nv_bfloat16(*Bh)[40] =
            (const __nv_bfloat16(*)[40])(sm + (ARR_BH * 2 + buf) * TS);
        const __nv_bfloat16(*Bl)[40] =
            (const __nv_bfloat16(*)[40])(sm + (ARR_BL * 2 + buf) * TS);

#pragma unroll
        for (int ks = 0; ks < 2; ks++) {
            const int kk = ks * 16 + tq * 2;
            uint32_t ah[2][4], al[2][4];
#pragma unroll
            for (int mt = 0; mt < 2; mt++) {
                const int m = warp_m + mt * 16 + tg;
                ah[mt][0] = *(const uint32_t*)&Ah[m][kk];
                ah[mt][1] = *(const uint32_t*)&Ah[m + 8][kk];
                ah[mt][2] = *(const uint32_t*)&Ah[m][kk + 8];
                ah[mt][3] = *(const uint32_t*)&Ah[m + 8][kk + 8];
                al[mt][0] = *(const uint32_t*)&Al[m][kk];
                al[mt][1] = *(const uint32_t*)&Al[m + 8][kk];
                al[mt][2] = *(const uint32_t*)&Al[m][kk + 8];
                al[mt][3] = *(const uint32_t*)&Al[m + 8][kk + 8];
            }
#pragma unroll
            for (int nt = 0; nt < 8; nt++) {
                const int n = warp_n + nt * 8 + tg;
                uint32_t bh0 = *(const uint32_t*)&Bh[n][kk];
                uint32_t bh1 = *(const uint32_t*)&Bh[n][kk + 8];
                uint32_t bl0 = *(const uint32_t*)&Bl[n][kk];
                uint32_t bl1 = *(const uint32_t*)&Bl[n][kk + 8];
#pragma unroll
                for (int mt = 0; mt < 2; mt++) {
                    mma16816(acc[mt][nt], ah[mt], bh0, bh1);
                    mma16816(acc[mt][nt], ah[mt], bl0, bl1);
                    mma16816(acc[mt][nt], al[mt], bh0, bh1);
                }
            }
        }
        __syncthreads();
    }

    // ---- epilogue: fragment -> d_K ----
#pragma unroll
    for (int mt = 0; mt < 2; mt++) {
        const int m = bm + warp_m + mt * 16 + tg;
#pragma unroll
        for (int nt = 0; nt < 8; nt++) {
            const int n = bn + warp_n + nt * 8 + tq * 2;
            *(float2*)&d_K[(size_t)m * 512 + n] =
                make_float2(acc[mt][nt][0], acc[mt][nt][1]);
            *(float2*)&d_K[(size_t)(m + 8) * 512 + n] =
                make_float2(acc[mt][nt][2], acc[mt][nt][3]);
        }
    }
}

// ---------------------------------------------------------------------------
// k2: KV[bh] += K[b,mrange,h,:]^T @ v[mrange,h,:]   (split over m, atomicAdd)
// ---------------------------------------------------------------------------
__global__ __launch_bounds__(256) void k2_kv(const float* __restrict__ v) {
    const int bh = blockIdx.x;
    const int b  = bh >> 3, h = bh & 7;
    const int ms = blockIdx.y;

    __shared__ __align__(16) float Ks[16][64];
    __shared__ __align__(16) float Vs[16][64];

    const int tid = threadIdx.x;
    const int td  = (tid >> 4) << 2;
    const int tl  = (tid & 15) << 2;
    const int lr  = tid >> 4;
    const int lc  = (tid & 15) << 2;

    unsigned long long acc[4][2];
#pragma unroll
    for (int i = 0; i < 4; i++) { acc[i][0] = 0ull; acc[i][1] = 0ull; }

    const float* Kb = d_K + (size_t)b * 2048 * 512 + h * 64;
    const float* Vb = v + h * 64;

    for (int m0 = ms * 128; m0 < ms * 128 + 128; m0 += 16) {
        *(float4*)&Ks[lr][lc] = *(const float4*)(Kb + (size_t)(m0 + lr) * 512 + lc);
        *(float4*)&Vs[lr][lc] = *(const float4*)(Vb + (size_t)(m0 + lr) * 512 + lc);
        __syncthreads();
#pragma unroll
        for (int mm = 0; mm < 16; mm++) {
            float kd[4];
            *(float4*)kd = *(float4*)&Ks[mm][td];
            unsigned long long v2[2];
            *(ulonglong2*)v2 = *(ulonglong2*)&Vs[mm][tl];
#pragma unroll
            for (int i = 0; i < 4; i++) {
                unsigned long long a2 = splat2(kd[i]);
                fma2(acc[i][0], a2, v2[0]);
                fma2(acc[i][1], a2, v2[1]);
            }
        }
        __syncthreads();
    }

    float* KVp = d_KV + (size_t)bh * 4096;
#pragma unroll
    for (int i = 0; i < 4; i++)
#pragma unroll
        for (int j = 0; j < 2; j++) {
            float2 p = *(float2*)&acc[i][j];
            atomicAdd(&KVp[(td + i) * 64 + tl + 2 * j],     p.x);
            atomicAdd(&KVp[(td + i) * 64 + tl + 2 * j + 1], p.y);
        }
}

// ---------------------------------------------------------------------------
// k4f: fused k3+k4.
//   Per CTA (b, ct 0..7, js 0..3):
//     1. compute W2 slice W2s[j 0..127][e 0..63] = SCALE * KV @ proj  (in smem)
//     2. Wfin[b, ct*64..+63, e] += Wq_slice @ W2s  (atomicAdd)
// ---------------------------------------------------------------------------
__global__ __launch_bounds__(256) void k4f(const float* __restrict__ proj,
                                           const float* __restrict__ qkv) {
    const int b  = blockIdx.x;
    const int ct = blockIdx.y;
    const int js = blockIdx.z;

    __shared__ __align__(16) float PW[128][64];  // proj slice, reused as W2s
    __shared__ __align__(16) float Aq[16][68];

    const int tid = threadIdx.x;

    // stage proj rows js*128 .. +127 (covers heads js*2, js*2+1)
#pragma unroll
    for (int i = 0; i < 8; i++) {
        int idx = tid + i * 256;           // float4 granule 0..2047
        int r = idx >> 4, c4 = (idx & 15) << 2;
        *(float4*)&PW[r][c4] =
            *(const float4*)(proj + (size_t)(js * 128 + r) * 64 + c4);
    }
    __syncthreads();

    // compute W2 slice: thread -> row r = tid>>1, e-half eh = (tid&1)*32
    {
        const int r  = tid >> 1;
        const int eh = (tid & 1) * 32;
        const int hl = r >> 6, dd = r & 63;
        const float* kvrow =
            d_KV + ((size_t)(b * 8 + js * 2 + hl)) * 4096 + dd * 64;
        unsigned long long accw[16];
#pragma unroll
        for (int i = 0; i < 16; i++) accw[i] = 0ull;

        for (int l = 0; l < 64; l++) {
            unsigned long long kv2 = splat2(kvrow[l]);
            const float* prow = &PW[hl * 64 + l][eh];
#pragma unroll
            for (int i = 0; i < 8; i++) {
                ulonglong2 p2 = *(const ulonglong2*)(prow + 4 * i);
                fma2(accw[2 * i],     kv2, p2.x);
                fma2(accw[2 * i + 1], kv2, p2.y);
            }
        }
        __syncthreads();   // done reading PW as proj
        float* dstr = &PW[r][eh];
#pragma unroll
        for (int i = 0; i < 16; i++) {
            float2 p = *(float2*)&accw[i];
            dstr[2 * i]     = SCALE * p.x;
            dstr[2 * i + 1] = SCALE * p.y;
        }
    }
    __syncthreads();       // PW now holds W2s

    // main loop: Wfin slice += Wq[c, j] * W2s[j][e]
    const int tc = (tid >> 4) << 2;
    const int te = (tid & 15) << 2;
    unsigned long long acc[4][2];
#pragma unroll
    for (int i = 0; i < 4; i++) { acc[i][0] = 0ull; acc[i][1] = 0ull; }

    for (int j0 = 0; j0 < 128; j0 += 16) {
        {
            int r  = tid >> 2;
            int c4 = (tid & 3) << 2;
            int c  = ct * 64 + r;
            int j  = js * 128 + j0 + c4;
            float4 a = *(const float4*)(qkv + ((size_t)c << 10) +
                                        ((j >> 6) << 7) + (j & 63));
            Aq[c4 + 0][r] = a.x; Aq[c4 + 1][r] = a.y;
            Aq[c4 + 2][r] = a.z; Aq[c4 + 3][r] = a.w;
        }
        __syncthreads();
#pragma unroll
        for (int jj = 0; jj < 16; jj++) {
            float a[4];
            *(float4*)a = *(float4*)&Aq[jj][tc];
            unsigned long long b2[2];
            *(ulonglong2*)b2 = *(const ulonglong2*)&PW[j0 + jj][te];
#pragma unroll
            for (int i = 0; i < 4; i++) {
                unsigned long long a2 = splat2(a[i]);
                fma2(acc[i][0], a2, b2[0]);
                fma2(acc[i][1], a2, b2[1]);
            }
        }
        __syncthreads();
    }

#pragma unroll
    for (int i = 0; i < 4; i++)
#pragma unroll
        for (int j = 0; j < 2; j++) {
            float2 p = *(float2*)&acc[i][j];
            float* dst = &d_Wfin[((size_t)b * 512 + ct * 64 + tc + i) * 64 + te + 2 * j];
            atomicAdd(dst,     p.x);
            atomicAdd(dst + 1, p.y);
        }
}

// ---------------------------------------------------------------------------
// k5: out[b,n,e] += Σ_c x[b,n,c] Wfin[b,c,e]   (split-K over c, atomicAdd)
// ---------------------------------------------------------------------------
__global__ __launch_bounds__(256) void k5_out(const float* __restrict__ x,
                                              float* __restrict__ out) {
    const int b  = blockIdx.x;
    const int nt = blockIdx.y;
    const int ks = blockIdx.z;

    __shared__ __align__(16) float Xs[16][68];
    __shared__ __align__(16) float Ws[16][64];

    const int tid = threadIdx.x;
    const int tn  = (tid >> 4) << 2;
    const int te  = (tid & 15) << 2;
    unsigned long long acc[4][2];
#pragma unroll
    for (int i = 0; i < 4; i++) { acc[i][0] = 0ull; acc[i][1] = 0ull; }

    for (int c0 = ks * 128; c0 < ks * 128 + 128; c0 += 16) {
        {
            int r  = tid >> 2;
            int c4 = (tid & 3) << 2;
            float4 a = *(const float4*)(x + ((size_t)(b * 2048 + nt * 64 + r) << 9) +
                                        c0 + c4);
            Xs[c4 + 0][r] = a.x; Xs[c4 + 1][r] = a.y;
            Xs[c4 + 2][r] = a.z; Xs[c4 + 3][r] = a.w;
        }
        {
            int cr = tid >> 4;
            int e4 = (tid & 15) << 2;
            *(float4*)&Ws[cr][e4] =
                *(const float4*)(d_Wfin + ((size_t)b * 512 + c0 + cr) * 64 + e4);
        }
        __syncthreads();
#pragma unroll
        for (int cc = 0; cc < 16; cc++) {
            float a[4];
            *(float4*)a = *(float4*)&Xs[cc][tn];
            unsigned long long b2[2];
            *(ulonglong2*)b2 = *(ulonglong2*)&Ws[cc][te];
#pragma unroll
            for (int i = 0; i < 4; i++) {
                unsigned long long a2 = splat2(a[i]);
                fma2(acc[i][0], a2, b2[0]);
                fma2(acc[i][1], a2, b2[1]);
            }
        }
        __syncthreads();
    }

#pragma unroll
    for (int i = 0; i < 4; i++)
#pragma unroll
        for (int j = 0; j < 2; j++) {
            float2 p = *(float2*)&acc[i][j];
            float* dst = &out[((size_t)(b * 2048 + nt * 64 + tn + i)) * 64 + te + 2 * j];
            atomicAdd(dst,     p.x);
            atomicAdd(dst + 1, p.y);
        }
}

// ---------------------------------------------------------------------------
extern "C" void kernel_launch(void* const* d_in, const int* in_sizes, int n_in,
                              void* d_out, int out_size) {
    const float* x    = (const float*)d_in[0];  // [4, 2048, 512]
    const float* v    = (const float*)d_in[1];  // [2048, 8, 64]
    const float* qkv  = (const float*)d_in[2];  // [512, 1024]
    const float* proj = (const float*)d_in[3];  // [512, 64]
    float* out = (float*)d_out;                 // [4, 2048, 64]

    cudaFuncSetAttribute(k1_mma, cudaFuncAttributeMaxDynamicSharedMemorySize,
                         K1_SMEM);

    k0_zero<<<2048, 256>>>(out);
    p_cvt_x<<<2048, 256>>>(x);
    p_cvt_w<<<128, 256>>>(qkv);
    k1_mma<<<dim3(4, 64), 256, K1_SMEM>>>(0);    // profiled launch slot 3
    k2_kv<<<dim3(32, 16), 256>>>(v);
    k4f<<<dim3(4, 8, 4), 256>>>(proj, qkv);
    k5_out<<<dim3(4, 32, 4), 256>>>(x, out);
}

// round 6
// speedup vs baseline: 1.0456x; 1.0456x over previous
#include <cuda_runtime.h>
#include <cuda_bf16.h>
#include <cstdint>

// ============================================================================
// VLunchboxMHSA — linear-attention reassociation, tensor-core k1.
// R6: ldmatrix fragment loads in k1; conversions fused into k0.
// ============================================================================

#define SCALE 0.125f

__device__ float d_K[4 * 2048 * 512];            // [b*m, h*64+d]
__device__ float d_KV[32 * 64 * 64];             // [bh, d, l]
__device__ float d_Wfin[4 * 512 * 64];           // [b, c, e]
__device__ __nv_bfloat16 d_xh[4 * 2048 * 512];   // x hi, [b*m][c]
__device__ __nv_bfloat16 d_xl[4 * 2048 * 512];   // x lo
__device__ __nv_bfloat16 d_wkh[512 * 512];       // Wk^T hi, [n=hd][k=c]
__device__ __nv_bfloat16 d_wkl[512 * 512];       // Wk^T lo

// ---------------- helpers ---------------------------------------------------
__device__ __forceinline__ uint32_t smem_u32(const void* p) {
    uint32_t a;
    asm("{ .reg .u64 t; cvta.to.shared.u64 t, %1; cvt.u32.u64 %0, t; }"
        : "=r"(a) : "l"(p));
    return a;
}
#define CP_ASYNC16(dst, src) \
    asm volatile("cp.async.ca.shared.global [%0], [%1], 16;" :: "r"(dst), "l"(src))
#define CP_COMMIT() asm volatile("cp.async.commit_group;" ::: "memory")
#define CP_WAIT(n)  asm volatile("cp.async.wait_group %0;" :: "n"(n) : "memory")

__device__ __forceinline__ void ldsm_x4(uint32_t& r0, uint32_t& r1,
                                        uint32_t& r2, uint32_t& r3,
                                        uint32_t addr) {
    asm volatile("ldmatrix.sync.aligned.m8n8.x4.shared.b16 {%0,%1,%2,%3}, [%4];"
                 : "=r"(r0), "=r"(r1), "=r"(r2), "=r"(r3) : "r"(addr));
}

__device__ __forceinline__ void mma16816(float* c, const uint32_t* a,
                                         uint32_t b0, uint32_t b1) {
    asm volatile(
        "mma.sync.aligned.m16n8k16.row.col.f32.bf16.bf16.f32 "
        "{%0,%1,%2,%3}, {%4,%5,%6,%7}, {%8,%9}, {%0,%1,%2,%3};"
        : "+f"(c[0]), "+f"(c[1]), "+f"(c[2]), "+f"(c[3])
        : "r"(a[0]), "r"(a[1]), "r"(a[2]), "r"(a[3]), "r"(b0), "r"(b1));
}

// split 8 floats into hi/lo bf16 (4x bf16x2 each)
__device__ __forceinline__ void split8(const float* f, uint4& hi, uint4& lo) {
    uint32_t h[4], l[4];
#pragma unroll
    for (int i = 0; i < 4; i++) {
        float2 p = make_float2(f[2 * i], f[2 * i + 1]);
        __nv_bfloat162 hb = __float22bfloat162_rn(p);
        float2 hr = __bfloat1622float2(hb);
        __nv_bfloat162 lb =
            __float22bfloat162_rn(make_float2(p.x - hr.x, p.y - hr.y));
        h[i] = *(uint32_t*)&hb;
        l[i] = *(uint32_t*)&lb;
    }
    hi = make_uint4(h[0], h[1], h[2], h[3]);
    lo = make_uint4(l[0], l[1], l[2], l[3]);
}

// packed f32x2 helpers (SIMT tail kernels)
__device__ __forceinline__ void fma2(unsigned long long& d,
                                     unsigned long long a,
                                     unsigned long long b) {
    asm("fma.rn.f32x2 %0, %1, %2, %0;" : "+l"(d) : "l"(a), "l"(b));
}
__device__ __forceinline__ unsigned long long splat2(float f) {
    unsigned long long r;
    unsigned u = __float_as_uint(f);
    asm("mov.b64 %0, {%1, %1};" : "=l"(r) : "r"(u));
    return r;
}

// ---------------------------------------------------------------------------
// k0: zero atomic buffers + convert x -> (xh,xl) + gather Wk -> (wkh,wkl)
//     grid 2048 x 256
// ---------------------------------------------------------------------------
__global__ __launch_bounds__(256) void k0_prep(const float* __restrict__ x,
                                               const float* __restrict__ qkv,
                                               float* __restrict__ out) {
    const int idx = blockIdx.x * 256 + threadIdx.x;   // 0..524287

    if (idx < 32 * 64 * 64)  d_KV[idx]   = 0.f;
    if (idx < 4 * 512 * 64)  d_Wfin[idx] = 0.f;
    if (idx < 4 * 2048 * 64) out[idx]    = 0.f;

    // x conversion: 8 elems per thread
    {
        size_t base = (size_t)idx * 8;
        float f[8];
        *(float4*)(f)     = *(const float4*)(x + base);
        *(float4*)(f + 4) = *(const float4*)(x + base + 4);
        uint4 hi, lo;
        split8(f, hi, lo);
        *(uint4*)(d_xh + base) = hi;
        *(uint4*)(d_xl + base) = lo;
    }

    // Wk gather+transpose+convert: first 32768 threads, 8 elems each
    if (idx < 32768) {
        int n  = idx >> 6;
        int kb = (idx & 63) * 8;
        int col = ((n >> 6) << 7) + 64 + (n & 63);
        float f[8];
#pragma unroll
        for (int j = 0; j < 8; j++)
            f[j] = qkv[(size_t)(kb + j) * 1024 + col];
        uint4 hi, lo;
        split8(f, hi, lo);
        *(uint4*)(d_wkh + (size_t)n * 512 + kb) = hi;
        *(uint4*)(d_wkl + (size_t)n * 512 + kb) = lo;
    }
}
__global__ void k_nop() {}

// ---------------------------------------------------------------------------
// k1_mma: K = x @ Wk  (M=8192, N=512, K=512) bf16 split-precision tensor core.
//   Pre-converted operands, cp.async double-buffer, ldmatrix fragment loads.
//   grid (4 n-tiles, 64 m-tiles), 256 thr, CTA tile 128x128, k-chunks of 32.
//   Tile buffer: [128 rows][40 bf16] (80 B row stride -> ldmatrix conflict-free)
// ---------------------------------------------------------------------------
#define TS 10240                       // bytes per tile buffer (128*40*2)
#define K1_SMEM (8 * TS)               // 4 arrays x 2 buffers = 81920 B
#define ARR_AH 0
#define ARR_AL 1
#define ARR_BH 2
#define ARR_BL 3

__global__ __launch_bounds__(256, 2) void k1_mma(int dummy) {
    extern __shared__ __align__(16) char sm[];
    const uint32_t sbase = smem_u32(sm);

    const int tid  = threadIdx.x;
    const int wid  = tid >> 5;
    const int lane = tid & 31;
    const int bm = blockIdx.y * 128;
    const int bn = blockIdx.x * 128;
    const int warp_m = (wid & 3) * 32;
    const int warp_n = (wid >> 2) * 64;
    const int tg = lane >> 2;   // 0..7
    const int tq = lane & 3;    // 0..3

    float acc[2][8][4];
#pragma unroll
    for (int mt = 0; mt < 2; mt++)
#pragma unroll
        for (int nt = 0; nt < 8; nt++)
#pragma unroll
            for (int i = 0; i < 4; i++) acc[mt][nt][i] = 0.f;

    // ldmatrix lane offset: row = lane&15, col granule = (lane>>4)*8 elems (16B)
    const uint32_t lm_off = (uint32_t)((lane & 15) * 80 + (lane >> 4) * 16);
    const uint32_t off_a  = (uint32_t)(warp_m * 80) + lm_off;
    const uint32_t off_b  = (uint32_t)(warp_n * 80) + lm_off;

    // cp.async granule coordinates (2 granules of 16B per array per thread)
    const int g_row0 = tid >> 2;
    const int g_row1 = g_row0 + 64;
    const int g_c    = tid & 3;

    auto issue = [&](int kc, int buf) {
        const int k0 = kc * 32;
#pragma unroll
        for (int i = 0; i < 2; i++) {
            const int row = i ? g_row1 : g_row0;
            const uint32_t doff = row * 80 + g_c * 16;
            const size_t aoff = (((size_t)(bm + row)) << 9) + k0 + g_c * 8;
            const size_t boff = (((size_t)(bn + row)) << 9) + k0 + g_c * 8;
            CP_ASYNC16(sbase + (ARR_AH * 2 + buf) * TS + doff,
                       (const char*)d_xh + aoff * 2);
            CP_ASYNC16(sbase + (ARR_AL * 2 + buf) * TS + doff,
                       (const char*)d_xl + aoff * 2);
            CP_ASYNC16(sbase + (ARR_BH * 2 + buf) * TS + doff,
                       (const char*)d_wkh + boff * 2);
            CP_ASYNC16(sbase + (ARR_BL * 2 + buf) * TS + doff,
                       (const char*)d_wkl + boff * 2);
        }
        CP_COMMIT();
    };

    issue(0, 0);

    for (int kc = 0; kc < 16; kc++) {
        const int buf = kc & 1;
        if (kc < 15) {
            issue(kc + 1, buf ^ 1);
            CP_WAIT(1);
        } else {
            CP_WAIT(0);
        }
        __syncthreads();

        const uint32_t bAh = sbase + (ARR_AH * 2 + buf) * TS;
        const uint32_t bAl = sbase + (ARR_AL * 2 + buf) * TS;
        const uint32_t bBh = sbase + (ARR_BH * 2 + buf) * TS;
        const uint32_t bBl = sbase + (ARR_BL * 2 + buf) * TS;

#pragma unroll
        for (int ks = 0; ks < 2; ks++) {
            const uint32_t kb = ks * 32;   // 16 bf16 = 32 bytes
            uint32_t ah[2][4], al[2][4];
#pragma unroll
            for (int mt = 0; mt < 2; mt++) {
                ldsm_x4(ah[mt][0], ah[mt][1], ah[mt][2], ah[mt][3],
                        bAh + off_a + mt * (16 * 80) + kb);
                ldsm_x4(al[mt][0], al[mt][1], al[mt][2], al[mt][3],
                        bAl + off_a + mt * (16 * 80) + kb);
            }
#pragma unroll
            for (int p = 0; p < 4; p++) {
                uint32_t bh4[4], bl4[4];
                ldsm_x4(bh4[0], bh4[1], bh4[2], bh4[3],
                        bBh + off_b + p * (16 * 80) + kb);
                ldsm_x4(bl4[0], bl4[1], bl4[2], bl4[3],
                        bBl + off_b + p * (16 * 80) + kb);
#pragma unroll
                for (int duo = 0; duo < 2; duo++) {
                    const int nt = 2 * p + duo;
                    const uint32_t b0h = bh4[duo], b1h = bh4[duo + 2];
                    const uint32_t b0l = bl4[duo], b1l = bl4[duo + 2];
#pragma unroll
                    for (int mt = 0; mt < 2; mt++) {
                        mma16816(acc[mt][nt], ah[mt], b0h, b1h);
                        mma16816(acc[mt][nt], ah[mt], b0l, b1l);
                        mma16816(acc[mt][nt], al[mt], b0h, b1h);
                    }
                }
            }
        }
        __syncthreads();
    }

    // ---- epilogue: fragment -> d_K ----
#pragma unroll
    for (int mt = 0; mt < 2; mt++) {
        const int m = bm + warp_m + mt * 16 + tg;
#pragma unroll
        for (int nt = 0; nt < 8; nt++) {
            const int n = bn + warp_n + nt * 8 + tq * 2;
            *(float2*)&d_K[(size_t)m * 512 + n] =
                make_float2(acc[mt][nt][0], acc[mt][nt][1]);
            *(float2*)&d_K[(size_t)(m + 8) * 512 + n] =
                make_float2(acc[mt][nt][2], acc[mt][nt][3]);
        }
    }
}

// ---------------------------------------------------------------------------
// k2: KV[bh] += K[b,mrange,h,:]^T @ v[mrange,h,:]   (split over m, atomicAdd)
// ---------------------------------------------------------------------------
__global__ __launch_bounds__(256) void k2_kv(const float* __restrict__ v) {
    const int bh = blockIdx.x;
    const int b  = bh >> 3, h = bh & 7;
    const int ms = blockIdx.y;

    __shared__ __align__(16) float Ks[16][64];
    __shared__ __align__(16) float Vs[16][64];

    const int tid = threadIdx.x;
    const int td  = (tid >> 4) << 2;
    const int tl  = (tid & 15) << 2;
    const int lr  = tid >> 4;
    const int lc  = (tid & 15) << 2;

    unsigned long long acc[4][2];
#pragma unroll
    for (int i = 0; i < 4; i++) { acc[i][0] = 0ull; acc[i][1] = 0ull; }

    const float* Kb = d_K + (size_t)b * 2048 * 512 + h * 64;
    const float* Vb = v + h * 64;

    for (int m0 = ms * 128; m0 < ms * 128 + 128; m0 += 16) {
        *(float4*)&Ks[lr][lc] = *(const float4*)(Kb + (size_t)(m0 + lr) * 512 + lc);
        *(float4*)&Vs[lr][lc] = *(const float4*)(Vb + (size_t)(m0 + lr) * 512 + lc);
        __syncthreads();
#pragma unroll
        for (int mm = 0; mm < 16; mm++) {
            float kd[4];
            *(float4*)kd = *(float4*)&Ks[mm][td];
            unsigned long long v2[2];
            *(ulonglong2*)v2 = *(ulonglong2*)&Vs[mm][tl];
#pragma unroll
            for (int i = 0; i < 4; i++) {
                unsigned long long a2 = splat2(kd[i]);
                fma2(acc[i][0], a2, v2[0]);
                fma2(acc[i][1], a2, v2[1]);
            }
        }
        __syncthreads();
    }

    float* KVp = d_KV + (size_t)bh * 4096;
#pragma unroll
    for (int i = 0; i < 4; i++)
#pragma unroll
        for (int j = 0; j < 2; j++) {
            float2 p = *(float2*)&acc[i][j];
            atomicAdd(&KVp[(td + i) * 64 + tl + 2 * j],     p.x);
            atomicAdd(&KVp[(td + i) * 64 + tl + 2 * j + 1], p.y);
        }
}

// ---------------------------------------------------------------------------
// k4f: fused k3+k4.
// ---------------------------------------------------------------------------
__global__ __launch_bounds__(256) void k4f(const float* __restrict__ proj,
                                           const float* __restrict__ qkv) {
    const int b  = blockIdx.x;
    const int ct = blockIdx.y;
    const int js = blockIdx.z;

    __shared__ __align__(16) float PW[128][64];  // proj slice, reused as W2s
    __shared__ __align__(16) float Aq[16][68];

    const int tid = threadIdx.x;

#pragma unroll
    for (int i = 0; i < 8; i++) {
        int idx = tid + i * 256;
        int r = idx >> 4, c4 = (idx & 15) << 2;
        *(float4*)&PW[r][c4] =
            *(const float4*)(proj + (size_t)(js * 128 + r) * 64 + c4);
    }
    __syncthreads();

    {
        const int r  = tid >> 1;
        const int eh = (tid & 1) * 32;
        const int hl = r >> 6, dd = r & 63;
        const float* kvrow =
            d_KV + ((size_t)(b * 8 + js * 2 + hl)) * 4096 + dd * 64;
        unsigned long long accw[16];
#pragma unroll
        for (int i = 0; i < 16; i++) accw[i] = 0ull;

        for (int l = 0; l < 64; l++) {
            unsigned long long kv2 = splat2(kvrow[l]);
            const float* prow = &PW[hl * 64 + l][eh];
#pragma unroll
            for (int i = 0; i < 8; i++) {
                ulonglong2 p2 = *(const ulonglong2*)(prow + 4 * i);
                fma2(accw[2 * i],     kv2, p2.x);
                fma2(accw[2 * i + 1], kv2, p2.y);
            }
        }
        __syncthreads();
        float* dstr = &PW[r][eh];
#pragma unroll
        for (int i = 0; i < 16; i++) {
            float2 p = *(float2*)&accw[i];
            dstr[2 * i]     = SCALE * p.x;
            dstr[2 * i + 1] = SCALE * p.y;
        }
    }
    __syncthreads();

    const int tc = (tid >> 4) << 2;
    const int te = (tid & 15) << 2;
    unsigned long long acc[4][2];
#pragma unroll
    for (int i = 0; i < 4; i++) { acc[i][0] = 0ull; acc[i][1] = 0ull; }

    for (int j0 = 0; j0 < 128; j0 += 16) {
        {
            int r  = tid >> 2;
            int c4 = (tid & 3) << 2;
            int c  = ct * 64 + r;
            int j  = js * 128 + j0 + c4;
            float4 a = *(const float4*)(qkv + ((size_t)c << 10) +
                                        ((j >> 6) << 7) + (j & 63));
            Aq[c4 + 0][r] = a.x; Aq[c4 + 1][r] = a.y;
            Aq[c4 + 2][r] = a.z; Aq[c4 + 3][r] = a.w;
        }
        __syncthreads();
#pragma unroll
        for (int jj = 0; jj < 16; jj++) {
            float a[4];
            *(float4*)a = *(float4*)&Aq[jj][tc];
            unsigned long long b2[2];
            *(ulonglong2*)b2 = *(const ulonglong2*)&PW[j0 + jj][te];
#pragma unroll
            for (int i = 0; i < 4; i++) {
                unsigned long long a2 = splat2(a[i]);
                fma2(acc[i][0], a2, b2[0]);
                fma2(acc[i][1], a2, b2[1]);
            }
        }
        __syncthreads();
    }

#pragma unroll
    for (int i = 0; i < 4; i++)
#pragma unroll
        for (int j = 0; j < 2; j++) {
            float2 p = *(float2*)&acc[i][j];
            float* dst = &d_Wfin[((size_t)b * 512 + ct * 64 + tc + i) * 64 + te + 2 * j];
            atomicAdd(dst,     p.x);
            atomicAdd(dst + 1, p.y);
        }
}

// ---------------------------------------------------------------------------
// k5: out[b,n,e] += Σ_c x[b,n,c] Wfin[b,c,e]   (split-K over c, atomicAdd)
// ---------------------------------------------------------------------------
__global__ __launch_bounds__(256) void k5_out(const float* __restrict__ x,
                                              float* __restrict__ out) {
    const int b  = blockIdx.x;
    const int nt = blockIdx.y;
    const int ks = blockIdx.z;

    __shared__ __align__(16) float Xs[16][68];
    __shared__ __align__(16) float Ws[16][64];

    const int tid = threadIdx.x;
    const int tn  = (tid >> 4) << 2;
    const int te  = (tid & 15) << 2;
    unsigned long long acc[4][2];
#pragma unroll
    for (int i = 0; i < 4; i++) { acc[i][0] = 0ull; acc[i][1] = 0ull; }

    for (int c0 = ks * 128; c0 < ks * 128 + 128; c0 += 16) {
        {
            int r  = tid >> 2;
            int c4 = (tid & 3) << 2;
            float4 a = *(const float4*)(x + ((size_t)(b * 2048 + nt * 64 + r) << 9) +
                                        c0 + c4);
            Xs[c4 + 0][r] = a.x; Xs[c4 + 1][r] = a.y;
            Xs[c4 + 2][r] = a.z; Xs[c4 + 3][r] = a.w;
        }
        {
            int cr = tid >> 4;
            int e4 = (tid & 15) << 2;
            *(float4*)&Ws[cr][e4] =
                *(const float4*)(d_Wfin + ((size_t)b * 512 + c0 + cr) * 64 + e4);
        }
        __syncthreads();
#pragma unroll
        for (int cc = 0; cc < 16; cc++) {
            float a[4];
            *(float4*)a = *(float4*)&Xs[cc][tn];
            unsigned long long b2[2];
            *(ulonglong2*)b2 = *(ulonglong2*)&Ws[cc][te];
#pragma unroll
            for (int i = 0; i < 4; i++) {
                unsigned long long a2 = splat2(a[i]);
                fma2(acc[i][0], a2, b2[0]);
                fma2(acc[i][1], a2, b2[1]);
            }
        }
        __syncthreads();
    }

#pragma unroll
    for (int i = 0; i < 4; i++)
#pragma unroll
        for (int j = 0; j < 2; j++) {
            float2 p = *(float2*)&acc[i][j];
            float* dst = &out[((size_t)(b * 2048 + nt * 64 + tn + i)) * 64 + te + 2 * j];
            atomicAdd(dst,     p.x);
            atomicAdd(dst + 1, p.y);
        }
}

// ---------------------------------------------------------------------------
extern "C" void kernel_launch(void* const* d_in, const int* in_sizes, int n_in,
                              void* d_out, int out_size) {
    const float* x    = (const float*)d_in[0];  // [4, 2048, 512]
    const float* v    = (const float*)d_in[1];  // [2048, 8, 64]
    const float* qkv  = (const float*)d_in[2];  // [512, 1024]
    const float* proj = (const float*)d_in[3];  // [512, 64]
    float* out = (float*)d_out;                 // [4, 2048, 64]

    cudaFuncSetAttribute(k1_mma, cudaFuncAttributeMaxDynamicSharedMemorySize,
                         K1_SMEM);

    k0_prep<<<2048, 256>>>(x, qkv, out);
    k_nop<<<1, 32>>>();
    k_nop<<<1, 32>>>();                          // k1_mma -> profiled slot 3
    k1_mma<<<dim3(4, 64), 256, K1_SMEM>>>(0);
    k2_kv<<<dim3(32, 16), 256>>>(v);
    k4f<<<dim3(4, 8, 4), 256>>>(proj, qkv);
    k5_out<<<dim3(4, 32, 4), 256>>>(x, out);
}